// round 14
// baseline (speedup 1.0000x reference)
#include <cuda_runtime.h>
#include <cuda_bf16.h>
#include <mma.h>
#include <cstdint>

using namespace nvcuda;

#define VOCAB 50257
#define EMBED 256
#define HID   128
#define G4    512   // 4*HID
#define BATCH 128
#define SEQ   1024

// Gate-projection table: table[v][g] = sum_e emb[v][e]*W_ih[g][e] + b_ih[g]+b_hh[g]
__device__ float g_table[(size_t)VOCAB * G4];
// pre-converted bf16 hi/lo copies (split: x = hi + lo, lo = residual)
__device__ __nv_bfloat16 g_embh[(size_t)VOCAB * EMBED];
__device__ __nv_bfloat16 g_embl[(size_t)VOCAB * EMBED];
__device__ __nv_bfloat16 g_wih_h[(size_t)G4 * EMBED];
__device__ __nv_bfloat16 g_wih_l[(size_t)G4 * EMBED];

typedef unsigned long long ull;

// ---------------- helpers ----------------
__device__ __forceinline__ ull pack2(float lo, float hi) {
    ull r; asm("mov.b64 %0, {%1, %2};" : "=l"(r) : "f"(lo), "f"(hi)); return r;
}
__device__ __forceinline__ void unpack2(ull v, float& lo, float& hi) {
    asm("mov.b64 {%0, %1}, %2;" : "=f"(lo), "=f"(hi) : "l"(v));
}
__device__ __forceinline__ void ffma2(ull& d, ull a, ull b) {
    asm("fma.rn.f32x2 %0, %1, %2, %0;" : "+l"(d) : "l"(a), "l"(b));
}
__device__ __forceinline__ float tanhaf(float x) {
    float y; asm("tanh.approx.f32 %0, %1;" : "=f"(y) : "f"(x)); return y;
}
__device__ __forceinline__ ull bf2pair(unsigned w) {
    unsigned lo = w << 16;
    unsigned hi = w & 0xffff0000u;
    ull r; asm("mov.b64 %0, {%1, %2};" : "=l"(r) : "r"(lo), "r"(hi));
    return r;
}
__device__ __forceinline__ unsigned bfpack(float wlo, float whi) {
    unsigned r;
    asm("cvt.rn.bf16x2.f32 %0, %1, %2;" : "=r"(r) : "f"(whi), "f"(wlo));
    return r;
}

// =====================================================================
// Kernel 0: fp32 -> bf16 hi + residual-lo split (run once per tensor)
// =====================================================================
__global__ void __launch_bounds__(256) conv_split_kernel(
    const float* __restrict__ src,
    __nv_bfloat16* __restrict__ dsth,
    __nv_bfloat16* __restrict__ dstl,
    int n4)
{
    int i = blockIdx.x * 256 + threadIdx.x;
    int stride = gridDim.x * 256;
    for (; i < n4; i += stride) {
        float4 a = ((const float4*)src)[i];
        unsigned h01 = bfpack(a.x, a.y);
        unsigned h23 = bfpack(a.z, a.w);
        unsigned l01 = bfpack(a.x - __uint_as_float(h01 << 16),
                              a.y - __uint_as_float(h01 & 0xffff0000u));
        unsigned l23 = bfpack(a.z - __uint_as_float(h23 << 16),
                              a.w - __uint_as_float(h23 & 0xffff0000u));
        ((uint2*)dsth)[i] = make_uint2(h01, h23);
        ((uint2*)dstl)[i] = make_uint2(l01, l23);
    }
}

// =====================================================================
// Kernel 1 (tensor cores, wmma): table = emb @ W_ih^T + bias
// bf16x3 split: D = Ah@Bh + Ah@Bl + Al@Bh, inputs pre-converted.
// CTA covers 128 vocab rows and loops over ALL 4 gate 128-blocks
// (A tiles L2-hot across the loop). 256 thr (8 warps, 2x4), warp 64x32.
// =====================================================================
#define CT_K 64
#define ASTR 72                 // bf16 per SMEM tile row (stride)
#define TILE_B (128 * ASTR * 2) // 18432 B per tile
#define OFF_BIAS 0              // 512 floats = 2048 B
#define OFF_AH 2048
#define OFF_AL (OFF_AH + TILE_B)
#define OFF_BH (OFF_AL + TILE_B)
#define OFF_BL (OFF_BH + TILE_B)
#define TB_SMEM (OFF_BL + TILE_B)   // 75776 B
#define CSTR 132

__global__ void __launch_bounds__(256, 2) table_wmma_kernel(
    const float* __restrict__ b_ih,
    const float* __restrict__ b_hh)
{
    extern __shared__ char smem[];
    const int tid = threadIdx.x;
    const int wid = tid >> 5;
    const int wm = wid >> 2;        // 0..1  (vocab 64-block)
    const int wn = wid & 3;         // 0..3  (gate 32-block)
    const int v0 = blockIdx.x * 128;

    // stage all 512 biases once
    {
        float* Sb = (float*)(smem + OFF_BIAS);
        Sb[tid]       = b_ih[tid]       + b_hh[tid];
        Sb[tid + 256] = b_ih[tid + 256] + b_hh[tid + 256];
    }

    __nv_bfloat16* Ah = (__nv_bfloat16*)(smem + OFF_AH);
    __nv_bfloat16* Al = (__nv_bfloat16*)(smem + OFF_AL);
    __nv_bfloat16* Bh = (__nv_bfloat16*)(smem + OFF_BH);
    __nv_bfloat16* Bl = (__nv_bfloat16*)(smem + OFF_BL);

    // loader mapping: row = tid>>1 (0..127), col half = (tid&1)*32
    const int lr = tid >> 1;
    const int lch = (tid & 1) * 32;
    const int vrow = min(v0 + lr, VOCAB - 1);
    const size_t aoff = (size_t)vrow * EMBED + lch;
    const int dso = lr * (ASTR * 2) + lch * 2;   // SMEM dst byte offset

    for (int gblk = 0; gblk < 4; gblk++) {
        const int g0 = gblk * 128;
        const size_t boff = (size_t)(g0 + lr) * EMBED + lch;

        wmma::fragment<wmma::accumulator, 16, 16, 16, float> acc[4][2];
#pragma unroll
        for (int i = 0; i < 4; i++)
#pragma unroll
            for (int jj = 0; jj < 2; jj++)
                wmma::fill_fragment(acc[i][jj], 0.0f);

        for (int c = 0; c < EMBED / CT_K; c++) {
            const size_t ko = (size_t)c * CT_K;
#pragma unroll
            for (int i = 0; i < 4; i++) {
                ((uint4*)((char*)Ah + dso))[i] = ((const uint4*)(g_embh  + aoff + ko))[i];
                ((uint4*)((char*)Al + dso))[i] = ((const uint4*)(g_embl  + aoff + ko))[i];
                ((uint4*)((char*)Bh + dso))[i] = ((const uint4*)(g_wih_h + boff + ko))[i];
                ((uint4*)((char*)Bl + dso))[i] = ((const uint4*)(g_wih_l + boff + ko))[i];
            }
            __syncthreads();

#pragma unroll
            for (int ks = 0; ks < 4; ks++) {
                const int k0 = ks * 16;
                wmma::fragment<wmma::matrix_b, 16, 16, 16, __nv_bfloat16, wmma::col_major> fBh[2], fBl[2];
#pragma unroll
                for (int jj = 0; jj < 2; jj++) {
                    const int gg = (wn * 32 + jj * 16) * ASTR + k0;
                    wmma::load_matrix_sync(fBh[jj], Bh + gg, ASTR);
                    wmma::load_matrix_sync(fBl[jj], Bl + gg, ASTR);
                }
#pragma unroll
                for (int i = 0; i < 4; i++) {
                    const int vv = (wm * 64 + i * 16) * ASTR + k0;
                    wmma::fragment<wmma::matrix_a, 16, 16, 16, __nv_bfloat16, wmma::row_major> fAh, fAl;
                    wmma::load_matrix_sync(fAh, Ah + vv, ASTR);
                    wmma::load_matrix_sync(fAl, Al + vv, ASTR);
#pragma unroll
                    for (int jj = 0; jj < 2; jj++) {
                        wmma::mma_sync(acc[i][jj], fAh, fBh[jj], acc[i][jj]);
                        wmma::mma_sync(acc[i][jj], fAh, fBl[jj], acc[i][jj]);
                        wmma::mma_sync(acc[i][jj], fAl, fBh[jj], acc[i][jj]);
                    }
                }
            }
            __syncthreads();
        }

        // ---- epilogue: accs -> SMEM C (reuses A tile region), bias, store ----
        float* C = (float*)(smem + OFF_AH);
#pragma unroll
        for (int i = 0; i < 4; i++)
#pragma unroll
            for (int jj = 0; jj < 2; jj++)
                wmma::store_matrix_sync(C + (wm * 64 + i * 16) * CSTR + wn * 32 + jj * 16,
                                        acc[i][jj], CSTR, wmma::mem_row_major);
        __syncthreads();

        {
            const int r = tid >> 1;
            const int cb = (tid & 1) * 64;
            const int v = v0 + r;
            if (v < VOCAB) {
                const float* Sb = (const float*)(smem + OFF_BIAS) + g0;
                float* dst = g_table + (size_t)v * G4 + g0 + cb;
                const float* src = C + r * CSTR + cb;
#pragma unroll
                for (int f = 0; f < 16; f++) {
                    float4 o = *(const float4*)(src + 4 * f);
                    o.x += Sb[cb + 4 * f + 0];
                    o.y += Sb[cb + 4 * f + 1];
                    o.z += Sb[cb + 4 * f + 2];
                    o.w += Sb[cb + 4 * f + 3];
                    *(float4*)(dst + 4 * f) = o;
                }
            }
        }
        __syncthreads();   // C region becomes A tile again next gblk
    }
}

// =====================================================================
// Kernel 2: per-batch LSTM recurrence (measured-best config, FROZEN).
// =====================================================================
#define HSKB 148

struct __align__(16) LstmSmem {
    uint4 wsb[6][512];
    float hsk[2][HSKB];
    float hred[256];
    int   toff[SEQ + 2];
};

__global__ void __launch_bounds__(512, 1) lstm_kernel(
    const void* __restrict__ xraw,
    const float* __restrict__ W_hh,
    const float* __restrict__ W_fc,
    const float* __restrict__ b_fc,
    float* __restrict__ out)
{
    extern __shared__ char smem_raw[];
    LstmSmem* S = (LstmSmem*)smem_raw;

    const int b = blockIdx.x;
    const int tid = threadIdx.x;
    const int j = tid >> 2;
    const int q = tid & 3;

    bool is64;
    {
        const int* xi = (const int*)xraw;
        int val = xi[2 * (tid & 31) + 1];
        unsigned m = __ballot_sync(0xffffffffu, val != 0);
        is64 = (m == 0u);
    }

    if (is64) {
        const long long* x64 = (const long long*)xraw + (size_t)b * SEQ;
        for (int i = tid; i <= SEQ; i += 512) {
            int src = min(i, SEQ - 1);
            S->toff[i] = ((int)x64[src]) << 11;
        }
    } else {
        const int* x32 = (const int*)xraw + (size_t)b * SEQ;
        for (int i = tid; i <= SEQ; i += 512) {
            int src = min(i, SEQ - 1);
            S->toff[i] = x32[src] << 11;
        }
    }

    ull wreg[40];
#pragma unroll
    for (int m = 0; m < 2; m++) {
        const float4* src = (const float4*)(W_hh + (size_t)((q ^ m) * HID + j) * HID + q * 32);
#pragma unroll
        for (int u = 0; u < 8; u++) {
            float4 w = src[u];
            wreg[m * 16 + 2 * u]     = pack2(w.x, w.y);
            wreg[m * 16 + 2 * u + 1] = pack2(w.z, w.w);
        }
    }
    {
        const float4* src = (const float4*)(W_hh + (size_t)((q ^ 2) * HID + j) * HID + q * 32);
#pragma unroll
        for (int u = 0; u < 4; u++) {
            float4 w = src[u];
            wreg[32 + 2 * u]     = pack2(w.x, w.y);
            wreg[32 + 2 * u + 1] = pack2(w.z, w.w);
        }
#pragma unroll
        for (int u2 = 0; u2 < 2; u2++) {
            float4 w0 = src[4 + 2 * u2];
            float4 w1 = src[5 + 2 * u2];
            uint4 pk;
            pk.x = bfpack(w0.x, w0.y);
            pk.y = bfpack(w0.z, w0.w);
            pk.z = bfpack(w1.x, w1.y);
            pk.w = bfpack(w1.z, w1.w);
            S->wsb[4 + u2][tid] = pk;
        }
    }
    {
        const float4* src = (const float4*)(W_hh + (size_t)((q ^ 3) * HID + j) * HID + q * 32);
#pragma unroll
        for (int u = 0; u < 4; u++) {
            float4 w0 = src[2 * u];
            float4 w1 = src[2 * u + 1];
            uint4 pk;
            pk.x = bfpack(w0.x, w0.y);
            pk.y = bfpack(w0.z, w0.w);
            pk.z = bfpack(w1.x, w1.y);
            pk.w = bfpack(w1.z, w1.w);
            S->wsb[u][tid] = pk;
        }
    }

    for (int i = tid; i < 2 * HSKB; i += 512) ((float*)S->hsk)[i] = 0.0f;

    float c = 0.0f;
    const float sc  = (q == 2) ? 1.0f : 0.5f;
    const float scb = (q == 2) ? 0.0f : 0.5f;
    const bool hwriter = (q == (j >> 5));
    const int hwidx = q * 36 + (j & 31);
    __syncthreads();

    const char* tabq = (const char*)g_table + (size_t)(q * HID + j) * 4;
    float xgq = *(const float*)(tabq + S->toff[0]);

    const float* hbase = S->hsk[0] + q * 36;
    const uint4* wsp = &S->wsb[0][tid];

    for (int t = 0; t < SEQ; t++) {
        const ulonglong2* hp = (const ulonglong2*)(hbase + (t & 1) * HSKB);
        float xg_nxt = *(const float*)(tabq + S->toff[t + 1]);

        ull acc0 = pack2(xgq, 0.0f);
        ull acc1 = 0ull, acc2 = 0ull, acc3 = 0ull;
#pragma unroll
        for (int u = 0; u < 4; u++) {
            uint4 wv = wsp[u * 512];
            ulonglong2 hv0 = hp[2 * u];
            ulonglong2 hv1 = hp[2 * u + 1];
            ffma2(acc0, wreg[4 * u],          hv0.x);
            ffma2(acc1, wreg[16 + 4 * u],     hv0.x);
            ffma2(acc0, wreg[4 * u + 1],      hv0.y);
            ffma2(acc1, wreg[16 + 4 * u + 1], hv0.y);
            ffma2(acc0, wreg[4 * u + 2],      hv1.x);
            ffma2(acc1, wreg[16 + 4 * u + 2], hv1.x);
            ffma2(acc0, wreg[4 * u + 3],      hv1.y);
            ffma2(acc1, wreg[16 + 4 * u + 3], hv1.y);
            if (u < 2) {
                ffma2(acc2, wreg[32 + 4 * u],     hv0.x);
                ffma2(acc2, wreg[32 + 4 * u + 1], hv0.y);
                ffma2(acc2, wreg[32 + 4 * u + 2], hv1.x);
                ffma2(acc2, wreg[32 + 4 * u + 3], hv1.y);
            } else {
                uint4 wv2 = wsp[(4 + (u - 2)) * 512];
                ffma2(acc2, bf2pair(wv2.x), hv0.x);
                ffma2(acc2, bf2pair(wv2.y), hv0.y);
                ffma2(acc2, bf2pair(wv2.z), hv1.x);
                ffma2(acc2, bf2pair(wv2.w), hv1.y);
            }
            ffma2(acc3, bf2pair(wv.x), hv0.x);
            ffma2(acc3, bf2pair(wv.y), hv0.y);
            ffma2(acc3, bf2pair(wv.z), hv1.x);
            ffma2(acc3, bf2pair(wv.w), hv1.y);
        }

        float p0, p1, p2, p3, lo, hi;
        unpack2(acc0, lo, hi); p0 = lo + hi;
        unpack2(acc1, lo, hi); p1 = lo + hi;
        unpack2(acc2, lo, hi); p2 = lo + hi;
        unpack2(acc3, lo, hi); p3 = lo + hi;

        float s0 = p0 + __shfl_xor_sync(0xffffffffu, p1, 1);
        float s1 = p2 + __shfl_xor_sync(0xffffffffu, p3, 1);
        float z  = s0 + __shfl_xor_sync(0xffffffffu, s1, 2);

        float a = fmaf(sc, tanhaf(sc * z), scb);

        float gi_ = __shfl_sync(0xffffffffu, a, 0, 4);
        float gf_ = __shfl_sync(0xffffffffu, a, 1, 4);
        float gg_ = __shfl_sync(0xffffffffu, a, 2, 4);
        float go_ = __shfl_sync(0xffffffffu, a, 3, 4);

        c = fmaf(gf_, c, gi_ * gg_);
        float h = go_ * tanhaf(c);
        if (hwriter) S->hsk[(t + 1) & 1][hwidx] = h;

        xgq = xg_nxt;
        __syncthreads();
    }

    if (tid < 256) {
        int cls = tid >> 7;
        int jj  = tid & 127;
        float hv = S->hsk[0][(jj >> 5) * 36 + (jj & 31)];
        S->hred[tid] = hv * W_fc[cls * HID + jj];
    }
    __syncthreads();
    if (tid < 2) {
        float s = b_fc[tid];
#pragma unroll 8
        for (int jj = 0; jj < HID; jj++) s += S->hred[tid * HID + jj];
        out[b * 2 + tid] = s;
    }
}

// =====================================================================
extern "C" void kernel_launch(void* const* d_in, const int* in_sizes, int n_in,
                              void* d_out, int out_size)
{
    const void*  x     = d_in[0];
    const float* emb   = (const float*)d_in[1];
    const float* W_ih  = (const float*)d_in[2];
    const float* W_hh  = (const float*)d_in[3];
    const float* b_ih  = (const float*)d_in[4];
    const float* b_hh  = (const float*)d_in[5];
    const float* W_fc  = (const float*)d_in[6];
    const float* b_fc  = (const float*)d_in[7];
    float* out = (float*)d_out;

    __nv_bfloat16 *p_embh, *p_embl, *p_wih_h, *p_wih_l;
    cudaGetSymbolAddress((void**)&p_embh,  g_embh);
    cudaGetSymbolAddress((void**)&p_embl,  g_embl);
    cudaGetSymbolAddress((void**)&p_wih_h, g_wih_h);
    cudaGetSymbolAddress((void**)&p_wih_l, g_wih_l);

    conv_split_kernel<<<1024, 256>>>(emb,  p_embh,  p_embl,  (VOCAB * EMBED) / 4);
    conv_split_kernel<<<128,  256>>>(W_ih, p_wih_h, p_wih_l, (G4 * EMBED) / 4);

    cudaFuncSetAttribute(table_wmma_kernel, cudaFuncAttributeMaxDynamicSharedMemorySize, TB_SMEM);
    table_wmma_kernel<<<(VOCAB + 127) / 128, 256, TB_SMEM>>>(b_ih, b_hh);

    const int smem_bytes = (int)sizeof(LstmSmem);
    cudaFuncSetAttribute(lstm_kernel, cudaFuncAttributeMaxDynamicSharedMemorySize, smem_bytes);
    lstm_kernel<<<BATCH, 512, smem_bytes>>>(x, W_hh, W_fc, b_fc, out);
}

// round 15
// speedup vs baseline: 1.0456x; 1.0456x over previous
#include <cuda_runtime.h>
#include <cuda_bf16.h>
#include <mma.h>
#include <cstdint>

using namespace nvcuda;

#define VOCAB 50257
#define EMBED 256
#define HID   128
#define G4    512   // 4*HID
#define BATCH 128
#define SEQ   1024

// Gate-projection table: table[v][g] = sum_e emb[v][e]*W_ih[g][e] + b_ih[g]+b_hh[g]
__device__ float g_table[(size_t)VOCAB * G4];
// pre-converted bf16 hi/lo copies (split: x = hi + lo, lo = residual)
__device__ __nv_bfloat16 g_embh[(size_t)VOCAB * EMBED];
__device__ __nv_bfloat16 g_embl[(size_t)VOCAB * EMBED];
__device__ __nv_bfloat16 g_wih_h[(size_t)G4 * EMBED];
__device__ __nv_bfloat16 g_wih_l[(size_t)G4 * EMBED];

typedef unsigned long long ull;

// ---------------- helpers ----------------
__device__ __forceinline__ ull pack2(float lo, float hi) {
    ull r; asm("mov.b64 %0, {%1, %2};" : "=l"(r) : "f"(lo), "f"(hi)); return r;
}
__device__ __forceinline__ void unpack2(ull v, float& lo, float& hi) {
    asm("mov.b64 {%0, %1}, %2;" : "=f"(lo), "=f"(hi) : "l"(v));
}
__device__ __forceinline__ void ffma2(ull& d, ull a, ull b) {
    asm("fma.rn.f32x2 %0, %1, %2, %0;" : "+l"(d) : "l"(a), "l"(b));
}
__device__ __forceinline__ float tanhaf(float x) {
    float y; asm("tanh.approx.f32 %0, %1;" : "=f"(y) : "f"(x)); return y;
}
__device__ __forceinline__ ull bf2pair(unsigned w) {
    unsigned lo = w << 16;
    unsigned hi = w & 0xffff0000u;
    ull r; asm("mov.b64 %0, {%1, %2};" : "=l"(r) : "r"(lo), "r"(hi));
    return r;
}
__device__ __forceinline__ unsigned bfpack(float wlo, float whi) {
    unsigned r;
    asm("cvt.rn.bf16x2.f32 %0, %1, %2;" : "=r"(r) : "f"(whi), "f"(wlo));
    return r;
}
// branchless 4-way select
__device__ __forceinline__ float pick4(float v0, float v1, float v2, float v3, int d) {
    float a = (d & 1) ? v1 : v0;
    float b = (d & 1) ? v3 : v2;
    return (d & 2) ? b : a;
}

// =====================================================================
// Kernel 0: fp32 -> bf16 hi + residual-lo split (run once per tensor)
// =====================================================================
__global__ void __launch_bounds__(256) conv_split_kernel(
    const float* __restrict__ src,
    __nv_bfloat16* __restrict__ dsth,
    __nv_bfloat16* __restrict__ dstl,
    int n4)
{
    int i = blockIdx.x * 256 + threadIdx.x;
    int stride = gridDim.x * 256;
    for (; i < n4; i += stride) {
        float4 a = ((const float4*)src)[i];
        unsigned h01 = bfpack(a.x, a.y);
        unsigned h23 = bfpack(a.z, a.w);
        unsigned l01 = bfpack(a.x - __uint_as_float(h01 << 16),
                              a.y - __uint_as_float(h01 & 0xffff0000u));
        unsigned l23 = bfpack(a.z - __uint_as_float(h23 << 16),
                              a.w - __uint_as_float(h23 & 0xffff0000u));
        ((uint2*)dsth)[i] = make_uint2(h01, h23);
        ((uint2*)dstl)[i] = make_uint2(l01, l23);
    }
}

// =====================================================================
// Kernel 1 (tensor cores, wmma): table = emb @ W_ih^T + bias
// R13 configuration (measured best): grid 393x4, CTA tile 128x128,
// 256 thr (8 warps, 2x4), warp tile 64x32, inputs pre-converted.
// =====================================================================
#define CT_K 64
#define ASTR 72                 // bf16 per SMEM tile row (stride)
#define TILE_B (128 * ASTR * 2) // 18432 B per tile
#define OFF_BIAS 0
#define OFF_AH 1024
#define OFF_AL (OFF_AH + TILE_B)
#define OFF_BH (OFF_AL + TILE_B)
#define OFF_BL (OFF_BH + TILE_B)
#define TB_SMEM (OFF_BL + TILE_B)   // 74752 B
#define CSTR 132

__global__ void __launch_bounds__(256, 2) table_wmma_kernel(
    const float* __restrict__ b_ih,
    const float* __restrict__ b_hh)
{
    extern __shared__ char smem[];
    const int tid = threadIdx.x;
    const int wid = tid >> 5;
    const int wm = wid >> 2;        // 0..1  (vocab 64-block)
    const int wn = wid & 3;         // 0..3  (gate 32-block)
    const int v0 = blockIdx.x * 128;
    const int g0 = blockIdx.y * 128;

    if (tid < 128)
        ((float*)(smem + OFF_BIAS))[tid] = b_ih[g0 + tid] + b_hh[g0 + tid];

    __nv_bfloat16* Ah = (__nv_bfloat16*)(smem + OFF_AH);
    __nv_bfloat16* Al = (__nv_bfloat16*)(smem + OFF_AL);
    __nv_bfloat16* Bh = (__nv_bfloat16*)(smem + OFF_BH);
    __nv_bfloat16* Bl = (__nv_bfloat16*)(smem + OFF_BL);

    wmma::fragment<wmma::accumulator, 16, 16, 16, float> acc[4][2];
#pragma unroll
    for (int i = 0; i < 4; i++)
#pragma unroll
        for (int jj = 0; jj < 2; jj++)
            wmma::fill_fragment(acc[i][jj], 0.0f);

    const int lr = tid >> 1;
    const int lch = (tid & 1) * 32;
    const int vrow = min(v0 + lr, VOCAB - 1);
    const size_t aoff = (size_t)vrow * EMBED + lch;
    const size_t boff = (size_t)(g0 + lr) * EMBED + lch;
    const int dso = lr * (ASTR * 2) + lch * 2;

    for (int c = 0; c < EMBED / CT_K; c++) {
        const size_t ko = (size_t)c * CT_K;
#pragma unroll
        for (int i = 0; i < 4; i++) {
            ((uint4*)((char*)Ah + dso))[i] = ((const uint4*)(g_embh  + aoff + ko))[i];
            ((uint4*)((char*)Al + dso))[i] = ((const uint4*)(g_embl  + aoff + ko))[i];
            ((uint4*)((char*)Bh + dso))[i] = ((const uint4*)(g_wih_h + boff + ko))[i];
            ((uint4*)((char*)Bl + dso))[i] = ((const uint4*)(g_wih_l + boff + ko))[i];
        }
        __syncthreads();

#pragma unroll
        for (int ks = 0; ks < 4; ks++) {
            const int k0 = ks * 16;
            wmma::fragment<wmma::matrix_b, 16, 16, 16, __nv_bfloat16, wmma::col_major> fBh[2], fBl[2];
#pragma unroll
            for (int jj = 0; jj < 2; jj++) {
                const int gg = (wn * 32 + jj * 16) * ASTR + k0;
                wmma::load_matrix_sync(fBh[jj], Bh + gg, ASTR);
                wmma::load_matrix_sync(fBl[jj], Bl + gg, ASTR);
            }
#pragma unroll
            for (int i = 0; i < 4; i++) {
                const int vv = (wm * 64 + i * 16) * ASTR + k0;
                wmma::fragment<wmma::matrix_a, 16, 16, 16, __nv_bfloat16, wmma::row_major> fAh, fAl;
                wmma::load_matrix_sync(fAh, Ah + vv, ASTR);
                wmma::load_matrix_sync(fAl, Al + vv, ASTR);
#pragma unroll
                for (int jj = 0; jj < 2; jj++) {
                    wmma::mma_sync(acc[i][jj], fAh, fBh[jj], acc[i][jj]);
                    wmma::mma_sync(acc[i][jj], fAh, fBl[jj], acc[i][jj]);
                    wmma::mma_sync(acc[i][jj], fAl, fBh[jj], acc[i][jj]);
                }
            }
        }
        __syncthreads();
    }

    // ---- epilogue: accs -> SMEM C (reuses tile region), bias add, store ----
    float* C = (float*)(smem + OFF_AH);
#pragma unroll
    for (int i = 0; i < 4; i++)
#pragma unroll
        for (int jj = 0; jj < 2; jj++)
            wmma::store_matrix_sync(C + (wm * 64 + i * 16) * CSTR + wn * 32 + jj * 16,
                                    acc[i][jj], CSTR, wmma::mem_row_major);
    __syncthreads();

    {
        const int r = tid >> 1;
        const int cb = (tid & 1) * 64;
        const int v = v0 + r;
        if (v < VOCAB) {
            const float* Sb = (const float*)(smem + OFF_BIAS);
            float* dst = g_table + (size_t)v * G4 + g0 + cb;
            const float* src = C + r * CSTR + cb;
#pragma unroll
            for (int f = 0; f < 16; f++) {
                float4 o = *(const float4*)(src + 4 * f);
                o.x += Sb[cb + 4 * f + 0];
                o.y += Sb[cb + 4 * f + 1];
                o.z += Sb[cb + 4 * f + 2];
                o.w += Sb[cb + 4 * f + 3];
                *(float4*)(dst + 4 * f) = o;
            }
        }
    }
}

// =====================================================================
// Kernel 2: per-batch LSTM recurrence. Frozen config except the
// activation gather: 3 shfl_xor + pick4 (one fewer MIO op/step).
// =====================================================================
#define HSKB 148

struct __align__(16) LstmSmem {
    uint4 wsb[6][512];
    float hsk[2][HSKB];
    float hred[256];
    int   toff[SEQ + 2];
};

__global__ void __launch_bounds__(512, 1) lstm_kernel(
    const void* __restrict__ xraw,
    const float* __restrict__ W_hh,
    const float* __restrict__ W_fc,
    const float* __restrict__ b_fc,
    float* __restrict__ out)
{
    extern __shared__ char smem_raw[];
    LstmSmem* S = (LstmSmem*)smem_raw;

    const int b = blockIdx.x;
    const int tid = threadIdx.x;
    const int j = tid >> 2;
    const int q = tid & 3;

    bool is64;
    {
        const int* xi = (const int*)xraw;
        int val = xi[2 * (tid & 31) + 1];
        unsigned m = __ballot_sync(0xffffffffu, val != 0);
        is64 = (m == 0u);
    }

    if (is64) {
        const long long* x64 = (const long long*)xraw + (size_t)b * SEQ;
        for (int i = tid; i <= SEQ; i += 512) {
            int src = min(i, SEQ - 1);
            S->toff[i] = ((int)x64[src]) << 11;
        }
    } else {
        const int* x32 = (const int*)xraw + (size_t)b * SEQ;
        for (int i = tid; i <= SEQ; i += 512) {
            int src = min(i, SEQ - 1);
            S->toff[i] = x32[src] << 11;
        }
    }

    ull wreg[40];
#pragma unroll
    for (int m = 0; m < 2; m++) {
        const float4* src = (const float4*)(W_hh + (size_t)((q ^ m) * HID + j) * HID + q * 32);
#pragma unroll
        for (int u = 0; u < 8; u++) {
            float4 w = src[u];
            wreg[m * 16 + 2 * u]     = pack2(w.x, w.y);
            wreg[m * 16 + 2 * u + 1] = pack2(w.z, w.w);
        }
    }
    {
        const float4* src = (const float4*)(W_hh + (size_t)((q ^ 2) * HID + j) * HID + q * 32);
#pragma unroll
        for (int u = 0; u < 4; u++) {
            float4 w = src[u];
            wreg[32 + 2 * u]     = pack2(w.x, w.y);
            wreg[32 + 2 * u + 1] = pack2(w.z, w.w);
        }
#pragma unroll
        for (int u2 = 0; u2 < 2; u2++) {
            float4 w0 = src[4 + 2 * u2];
            float4 w1 = src[5 + 2 * u2];
            uint4 pk;
            pk.x = bfpack(w0.x, w0.y);
            pk.y = bfpack(w0.z, w0.w);
            pk.z = bfpack(w1.x, w1.y);
            pk.w = bfpack(w1.z, w1.w);
            S->wsb[4 + u2][tid] = pk;
        }
    }
    {
        const float4* src = (const float4*)(W_hh + (size_t)((q ^ 3) * HID + j) * HID + q * 32);
#pragma unroll
        for (int u = 0; u < 4; u++) {
            float4 w0 = src[2 * u];
            float4 w1 = src[2 * u + 1];
            uint4 pk;
            pk.x = bfpack(w0.x, w0.y);
            pk.y = bfpack(w0.z, w0.w);
            pk.z = bfpack(w1.x, w1.y);
            pk.w = bfpack(w1.z, w1.w);
            S->wsb[u][tid] = pk;
        }
    }

    for (int i = tid; i < 2 * HSKB; i += 512) ((float*)S->hsk)[i] = 0.0f;

    float c = 0.0f;
    const float sc  = (q == 2) ? 1.0f : 0.5f;
    const float scb = (q == 2) ? 0.0f : 0.5f;
    const bool hwriter = (q == (j >> 5));
    const int hwidx = q * 36 + (j & 31);
    __syncthreads();

    const char* tabq = (const char*)g_table + (size_t)(q * HID + j) * 4;
    float xgq = *(const float*)(tabq + S->toff[0]);

    const float* hbase = S->hsk[0] + q * 36;
    const uint4* wsp = &S->wsb[0][tid];

    for (int t = 0; t < SEQ; t++) {
        const ulonglong2* hp = (const ulonglong2*)(hbase + (t & 1) * HSKB);
        float xg_nxt = *(const float*)(tabq + S->toff[t + 1]);

        ull acc0 = pack2(xgq, 0.0f);
        ull acc1 = 0ull, acc2 = 0ull, acc3 = 0ull;
#pragma unroll
        for (int u = 0; u < 4; u++) {
            uint4 wv = wsp[u * 512];
            ulonglong2 hv0 = hp[2 * u];
            ulonglong2 hv1 = hp[2 * u + 1];
            ffma2(acc0, wreg[4 * u],          hv0.x);
            ffma2(acc1, wreg[16 + 4 * u],     hv0.x);
            ffma2(acc0, wreg[4 * u + 1],      hv0.y);
            ffma2(acc1, wreg[16 + 4 * u + 1], hv0.y);
            ffma2(acc0, wreg[4 * u + 2],      hv1.x);
            ffma2(acc1, wreg[16 + 4 * u + 2], hv1.x);
            ffma2(acc0, wreg[4 * u + 3],      hv1.y);
            ffma2(acc1, wreg[16 + 4 * u + 3], hv1.y);
            if (u < 2) {
                ffma2(acc2, wreg[32 + 4 * u],     hv0.x);
                ffma2(acc2, wreg[32 + 4 * u + 1], hv0.y);
                ffma2(acc2, wreg[32 + 4 * u + 2], hv1.x);
                ffma2(acc2, wreg[32 + 4 * u + 3], hv1.y);
            } else {
                uint4 wv2 = wsp[(4 + (u - 2)) * 512];
                ffma2(acc2, bf2pair(wv2.x), hv0.x);
                ffma2(acc2, bf2pair(wv2.y), hv0.y);
                ffma2(acc2, bf2pair(wv2.z), hv1.x);
                ffma2(acc2, bf2pair(wv2.w), hv1.y);
            }
            ffma2(acc3, bf2pair(wv.x), hv0.x);
            ffma2(acc3, bf2pair(wv.y), hv0.y);
            ffma2(acc3, bf2pair(wv.z), hv1.x);
            ffma2(acc3, bf2pair(wv.w), hv1.y);
        }

        float p0, p1, p2, p3, lo, hi;
        unpack2(acc0, lo, hi); p0 = lo + hi;
        unpack2(acc1, lo, hi); p1 = lo + hi;
        unpack2(acc2, lo, hi); p2 = lo + hi;
        unpack2(acc3, lo, hi); p3 = lo + hi;

        // ---- reduce: lane q ends with full z of gate q ----
        float s0 = p0 + __shfl_xor_sync(0xffffffffu, p1, 1);
        float s1 = p2 + __shfl_xor_sync(0xffffffffu, p3, 1);
        float z  = s0 + __shfl_xor_sync(0xffffffffu, s1, 2);

        // ---- activation: single tanh.approx per lane ----
        float a = fmaf(sc, tanhaf(sc * z), scb);

        // ---- gather via 3 xor-shfls + branchless selects ----
        float a1 = __shfl_xor_sync(0xffffffffu, a, 1);    // gate q^1
        float a2 = __shfl_xor_sync(0xffffffffu, a, 2);    // gate q^2
        float a3 = __shfl_xor_sync(0xffffffffu, a1, 2);   // gate q^3
        float gi_ = pick4(a, a1, a2, a3, q);
        float gf_ = pick4(a, a1, a2, a3, q ^ 1);
        float gg_ = pick4(a, a1, a2, a3, q ^ 2);
        float go_ = pick4(a, a1, a2, a3, q ^ 3);

        c = fmaf(gf_, c, gi_ * gg_);
        float h = go_ * tanhaf(c);
        if (hwriter) S->hsk[(t + 1) & 1][hwidx] = h;

        xgq = xg_nxt;
        __syncthreads();
    }

    if (tid < 256) {
        int cls = tid >> 7;
        int jj  = tid & 127;
        float hv = S->hsk[0][(jj >> 5) * 36 + (jj & 31)];
        S->hred[tid] = hv * W_fc[cls * HID + jj];
    }
    __syncthreads();
    if (tid < 2) {
        float s = b_fc[tid];
#pragma unroll 8
        for (int jj = 0; jj < HID; jj++) s += S->hred[tid * HID + jj];
        out[b * 2 + tid] = s;
    }
}

// =====================================================================
extern "C" void kernel_launch(void* const* d_in, const int* in_sizes, int n_in,
                              void* d_out, int out_size)
{
    const void*  x     = d_in[0];
    const float* emb   = (const float*)d_in[1];
    const float* W_ih  = (const float*)d_in[2];
    const float* W_hh  = (const float*)d_in[3];
    const float* b_ih  = (const float*)d_in[4];
    const float* b_hh  = (const float*)d_in[5];
    const float* W_fc  = (const float*)d_in[6];
    const float* b_fc  = (const float*)d_in[7];
    float* out = (float*)d_out;

    __nv_bfloat16 *p_embh, *p_embl, *p_wih_h, *p_wih_l;
    cudaGetSymbolAddress((void**)&p_embh,  g_embh);
    cudaGetSymbolAddress((void**)&p_embl,  g_embl);
    cudaGetSymbolAddress((void**)&p_wih_h, g_wih_h);
    cudaGetSymbolAddress((void**)&p_wih_l, g_wih_l);

    conv_split_kernel<<<1024, 256>>>(emb,  p_embh,  p_embl,  (VOCAB * EMBED) / 4);
    conv_split_kernel<<<128,  256>>>(W_ih, p_wih_h, p_wih_l, (G4 * EMBED) / 4);

    cudaFuncSetAttribute(table_wmma_kernel, cudaFuncAttributeMaxDynamicSharedMemorySize, TB_SMEM);
    dim3 tgrid((VOCAB + 127) / 128, G4 / 128);   // 393 x 4
    table_wmma_kernel<<<tgrid, 256, TB_SMEM>>>(b_ih, b_hh);

    const int smem_bytes = (int)sizeof(LstmSmem);
    cudaFuncSetAttribute(lstm_kernel, cudaFuncAttributeMaxDynamicSharedMemorySize, smem_bytes);
    lstm_kernel<<<BATCH, 512, smem_bytes>>>(x, W_hh, W_fc, b_fc, out);
}

// round 16
// speedup vs baseline: 1.0464x; 1.0008x over previous
#include <cuda_runtime.h>
#include <cuda_bf16.h>
#include <mma.h>
#include <cstdint>

using namespace nvcuda;

#define VOCAB 50257
#define EMBED 256
#define HID   128
#define G4    512   // 4*HID
#define BATCH 128
#define SEQ   1024

// Gate-projection table: table[v][g] = sum_e emb[v][e]*W_ih[g][e] + b_ih[g]+b_hh[g]
__device__ float g_table[(size_t)VOCAB * G4];
// pre-converted bf16 hi/lo copies (split: x = hi + lo, lo = residual)
__device__ __nv_bfloat16 g_embh[(size_t)VOCAB * EMBED];
__device__ __nv_bfloat16 g_embl[(size_t)VOCAB * EMBED];
__device__ __nv_bfloat16 g_wih_h[(size_t)G4 * EMBED];
__device__ __nv_bfloat16 g_wih_l[(size_t)G4 * EMBED];

typedef unsigned long long ull;

// ---------------- helpers ----------------
__device__ __forceinline__ ull pack2(float lo, float hi) {
    ull r; asm("mov.b64 %0, {%1, %2};" : "=l"(r) : "f"(lo), "f"(hi)); return r;
}
__device__ __forceinline__ void unpack2(ull v, float& lo, float& hi) {
    asm("mov.b64 {%0, %1}, %2;" : "=f"(lo), "=f"(hi) : "l"(v));
}
__device__ __forceinline__ void ffma2(ull& d, ull a, ull b) {
    asm("fma.rn.f32x2 %0, %1, %2, %0;" : "+l"(d) : "l"(a), "l"(b));
}
__device__ __forceinline__ float tanhaf(float x) {
    float y; asm("tanh.approx.f32 %0, %1;" : "=f"(y) : "f"(x)); return y;
}
__device__ __forceinline__ ull bf2pair(unsigned w) {
    unsigned lo = w << 16;
    unsigned hi = w & 0xffff0000u;
    ull r; asm("mov.b64 %0, {%1, %2};" : "=l"(r) : "r"(lo), "r"(hi));
    return r;
}
__device__ __forceinline__ unsigned bfpack(float wlo, float whi) {
    unsigned r;
    asm("cvt.rn.bf16x2.f32 %0, %1, %2;" : "=r"(r) : "f"(whi), "f"(wlo));
    return r;
}
// branchless 4-way select
__device__ __forceinline__ float pick4(float v0, float v1, float v2, float v3, int d) {
    float a = (d & 1) ? v1 : v0;
    float b = (d & 1) ? v3 : v2;
    return (d & 2) ? b : a;
}

// =====================================================================
// Kernel 0: fused fp32 -> bf16 hi/lo splits for emb AND W_ih
// =====================================================================
#define EMB_N4 ((VOCAB * EMBED) / 4)      // 3216448
#define WIH_N4 ((G4 * EMBED) / 4)         // 32768
#define CONV_BLOCKS 1160                  // ~ (EMB_N4 + WIH_N4) / (256*11)

__global__ void __launch_bounds__(256) conv_split_fused(
    const float* __restrict__ emb,
    const float* __restrict__ wih,
    __nv_bfloat16* __restrict__ embh,
    __nv_bfloat16* __restrict__ embl,
    __nv_bfloat16* __restrict__ wihh,
    __nv_bfloat16* __restrict__ wihl)
{
    const int total = EMB_N4 + WIH_N4;
    int i = blockIdx.x * 256 + threadIdx.x;
    int stride = gridDim.x * 256;
    for (; i < total; i += stride) {
        const float4* src;
        uint2 *dh, *dl;
        int idx;
        if (i < EMB_N4) {
            src = (const float4*)emb; dh = (uint2*)embh; dl = (uint2*)embl; idx = i;
        } else {
            src = (const float4*)wih; dh = (uint2*)wihh; dl = (uint2*)wihl; idx = i - EMB_N4;
        }
        float4 a = src[idx];
        unsigned h01 = bfpack(a.x, a.y);
        unsigned h23 = bfpack(a.z, a.w);
        unsigned l01 = bfpack(a.x - __uint_as_float(h01 << 16),
                              a.y - __uint_as_float(h01 & 0xffff0000u));
        unsigned l23 = bfpack(a.z - __uint_as_float(h23 << 16),
                              a.w - __uint_as_float(h23 & 0xffff0000u));
        dh[idx] = make_uint2(h01, h23);
        dl[idx] = make_uint2(l01, l23);
    }
}

// =====================================================================
// Kernel 1 (tensor cores, wmma): table = emb @ W_ih^T + bias
// R13/R15 body; grid SWAPPED to (4 gate-blocks, 393 vocab-blocks) so
// the 4 CTAs sharing a vocab block are bid-adjacent -> same wave ->
// emb hi/lo tiles fetched once into L2 and shared.
// =====================================================================
#define CT_K 64
#define ASTR 72                 // bf16 per SMEM tile row (stride)
#define TILE_B (128 * ASTR * 2) // 18432 B per tile
#define OFF_BIAS 0
#define OFF_AH 1024
#define OFF_AL (OFF_AH + TILE_B)
#define OFF_BH (OFF_AL + TILE_B)
#define OFF_BL (OFF_BH + TILE_B)
#define TB_SMEM (OFF_BL + TILE_B)   // 74752 B
#define CSTR 132

__global__ void __launch_bounds__(256, 2) table_wmma_kernel(
    const float* __restrict__ b_ih,
    const float* __restrict__ b_hh)
{
    extern __shared__ char smem[];
    const int tid = threadIdx.x;
    const int wid = tid >> 5;
    const int wm = wid >> 2;        // 0..1  (vocab 64-block)
    const int wn = wid & 3;         // 0..3  (gate 32-block)
    const int v0 = blockIdx.y * 128;
    const int g0 = blockIdx.x * 128;

    if (tid < 128)
        ((float*)(smem + OFF_BIAS))[tid] = b_ih[g0 + tid] + b_hh[g0 + tid];

    __nv_bfloat16* Ah = (__nv_bfloat16*)(smem + OFF_AH);
    __nv_bfloat16* Al = (__nv_bfloat16*)(smem + OFF_AL);
    __nv_bfloat16* Bh = (__nv_bfloat16*)(smem + OFF_BH);
    __nv_bfloat16* Bl = (__nv_bfloat16*)(smem + OFF_BL);

    wmma::fragment<wmma::accumulator, 16, 16, 16, float> acc[4][2];
#pragma unroll
    for (int i = 0; i < 4; i++)
#pragma unroll
        for (int jj = 0; jj < 2; jj++)
            wmma::fill_fragment(acc[i][jj], 0.0f);

    const int lr = tid >> 1;
    const int lch = (tid & 1) * 32;
    const int vrow = min(v0 + lr, VOCAB - 1);
    const size_t aoff = (size_t)vrow * EMBED + lch;
    const size_t boff = (size_t)(g0 + lr) * EMBED + lch;
    const int dso = lr * (ASTR * 2) + lch * 2;

    for (int c = 0; c < EMBED / CT_K; c++) {
        const size_t ko = (size_t)c * CT_K;
#pragma unroll
        for (int i = 0; i < 4; i++) {
            ((uint4*)((char*)Ah + dso))[i] = ((const uint4*)(g_embh  + aoff + ko))[i];
            ((uint4*)((char*)Al + dso))[i] = ((const uint4*)(g_embl  + aoff + ko))[i];
            ((uint4*)((char*)Bh + dso))[i] = ((const uint4*)(g_wih_h + boff + ko))[i];
            ((uint4*)((char*)Bl + dso))[i] = ((const uint4*)(g_wih_l + boff + ko))[i];
        }
        __syncthreads();

#pragma unroll
        for (int ks = 0; ks < 4; ks++) {
            const int k0 = ks * 16;
            wmma::fragment<wmma::matrix_b, 16, 16, 16, __nv_bfloat16, wmma::col_major> fBh[2], fBl[2];
#pragma unroll
            for (int jj = 0; jj < 2; jj++) {
                const int gg = (wn * 32 + jj * 16) * ASTR + k0;
                wmma::load_matrix_sync(fBh[jj], Bh + gg, ASTR);
                wmma::load_matrix_sync(fBl[jj], Bl + gg, ASTR);
            }
#pragma unroll
            for (int i = 0; i < 4; i++) {
                const int vv = (wm * 64 + i * 16) * ASTR + k0;
                wmma::fragment<wmma::matrix_a, 16, 16, 16, __nv_bfloat16, wmma::row_major> fAh, fAl;
                wmma::load_matrix_sync(fAh, Ah + vv, ASTR);
                wmma::load_matrix_sync(fAl, Al + vv, ASTR);
#pragma unroll
                for (int jj = 0; jj < 2; jj++) {
                    wmma::mma_sync(acc[i][jj], fAh, fBh[jj], acc[i][jj]);
                    wmma::mma_sync(acc[i][jj], fAh, fBl[jj], acc[i][jj]);
                    wmma::mma_sync(acc[i][jj], fAl, fBh[jj], acc[i][jj]);
                }
            }
        }
        __syncthreads();
    }

    // ---- epilogue: accs -> SMEM C (reuses tile region), bias add, store ----
    float* C = (float*)(smem + OFF_AH);
#pragma unroll
    for (int i = 0; i < 4; i++)
#pragma unroll
        for (int jj = 0; jj < 2; jj++)
            wmma::store_matrix_sync(C + (wm * 64 + i * 16) * CSTR + wn * 32 + jj * 16,
                                    acc[i][jj], CSTR, wmma::mem_row_major);
    __syncthreads();

    {
        const int r = tid >> 1;
        const int cb = (tid & 1) * 64;
        const int v = v0 + r;
        if (v < VOCAB) {
            const float* Sb = (const float*)(smem + OFF_BIAS);
            float* dst = g_table + (size_t)v * G4 + g0 + cb;
            const float* src = C + r * CSTR + cb;
#pragma unroll
            for (int f = 0; f < 16; f++) {
                float4 o = *(const float4*)(src + 4 * f);
                o.x += Sb[cb + 4 * f + 0];
                o.y += Sb[cb + 4 * f + 1];
                o.z += Sb[cb + 4 * f + 2];
                o.w += Sb[cb + 4 * f + 3];
                *(float4*)(dst + 4 * f) = o;
            }
        }
    }
}

// =====================================================================
// Kernel 2: per-batch LSTM recurrence (R15 measured-best, FROZEN).
// =====================================================================
#define HSKB 148

struct __align__(16) LstmSmem {
    uint4 wsb[6][512];
    float hsk[2][HSKB];
    float hred[256];
    int   toff[SEQ + 2];
};

__global__ void __launch_bounds__(512, 1) lstm_kernel(
    const void* __restrict__ xraw,
    const float* __restrict__ W_hh,
    const float* __restrict__ W_fc,
    const float* __restrict__ b_fc,
    float* __restrict__ out)
{
    extern __shared__ char smem_raw[];
    LstmSmem* S = (LstmSmem*)smem_raw;

    const int b = blockIdx.x;
    const int tid = threadIdx.x;
    const int j = tid >> 2;
    const int q = tid & 3;

    bool is64;
    {
        const int* xi = (const int*)xraw;
        int val = xi[2 * (tid & 31) + 1];
        unsigned m = __ballot_sync(0xffffffffu, val != 0);
        is64 = (m == 0u);
    }

    if (is64) {
        const long long* x64 = (const long long*)xraw + (size_t)b * SEQ;
        for (int i = tid; i <= SEQ; i += 512) {
            int src = min(i, SEQ - 1);
            S->toff[i] = ((int)x64[src]) << 11;
        }
    } else {
        const int* x32 = (const int*)xraw + (size_t)b * SEQ;
        for (int i = tid; i <= SEQ; i += 512) {
            int src = min(i, SEQ - 1);
            S->toff[i] = x32[src] << 11;
        }
    }

    ull wreg[40];
#pragma unroll
    for (int m = 0; m < 2; m++) {
        const float4* src = (const float4*)(W_hh + (size_t)((q ^ m) * HID + j) * HID + q * 32);
#pragma unroll
        for (int u = 0; u < 8; u++) {
            float4 w = src[u];
            wreg[m * 16 + 2 * u]     = pack2(w.x, w.y);
            wreg[m * 16 + 2 * u + 1] = pack2(w.z, w.w);
        }
    }
    {
        const float4* src = (const float4*)(W_hh + (size_t)((q ^ 2) * HID + j) * HID + q * 32);
#pragma unroll
        for (int u = 0; u < 4; u++) {
            float4 w = src[u];
            wreg[32 + 2 * u]     = pack2(w.x, w.y);
            wreg[32 + 2 * u + 1] = pack2(w.z, w.w);
        }
#pragma unroll
        for (int u2 = 0; u2 < 2; u2++) {
            float4 w0 = src[4 + 2 * u2];
            float4 w1 = src[5 + 2 * u2];
            uint4 pk;
            pk.x = bfpack(w0.x, w0.y);
            pk.y = bfpack(w0.z, w0.w);
            pk.z = bfpack(w1.x, w1.y);
            pk.w = bfpack(w1.z, w1.w);
            S->wsb[4 + u2][tid] = pk;
        }
    }
    {
        const float4* src = (const float4*)(W_hh + (size_t)((q ^ 3) * HID + j) * HID + q * 32);
#pragma unroll
        for (int u = 0; u < 4; u++) {
            float4 w0 = src[2 * u];
            float4 w1 = src[2 * u + 1];
            uint4 pk;
            pk.x = bfpack(w0.x, w0.y);
            pk.y = bfpack(w0.z, w0.w);
            pk.z = bfpack(w1.x, w1.y);
            pk.w = bfpack(w1.z, w1.w);
            S->wsb[u][tid] = pk;
        }
    }

    for (int i = tid; i < 2 * HSKB; i += 512) ((float*)S->hsk)[i] = 0.0f;

    float c = 0.0f;
    const float sc  = (q == 2) ? 1.0f : 0.5f;
    const float scb = (q == 2) ? 0.0f : 0.5f;
    const bool hwriter = (q == (j >> 5));
    const int hwidx = q * 36 + (j & 31);
    __syncthreads();

    const char* tabq = (const char*)g_table + (size_t)(q * HID + j) * 4;
    float xgq = *(const float*)(tabq + S->toff[0]);

    const float* hbase = S->hsk[0] + q * 36;
    const uint4* wsp = &S->wsb[0][tid];

    for (int t = 0; t < SEQ; t++) {
        const ulonglong2* hp = (const ulonglong2*)(hbase + (t & 1) * HSKB);
        float xg_nxt = *(const float*)(tabq + S->toff[t + 1]);

        ull acc0 = pack2(xgq, 0.0f);
        ull acc1 = 0ull, acc2 = 0ull, acc3 = 0ull;
#pragma unroll
        for (int u = 0; u < 4; u++) {
            uint4 wv = wsp[u * 512];
            ulonglong2 hv0 = hp[2 * u];
            ulonglong2 hv1 = hp[2 * u + 1];
            ffma2(acc0, wreg[4 * u],          hv0.x);
            ffma2(acc1, wreg[16 + 4 * u],     hv0.x);
            ffma2(acc0, wreg[4 * u + 1],      hv0.y);
            ffma2(acc1, wreg[16 + 4 * u + 1], hv0.y);
            ffma2(acc0, wreg[4 * u + 2],      hv1.x);
            ffma2(acc1, wreg[16 + 4 * u + 2], hv1.x);
            ffma2(acc0, wreg[4 * u + 3],      hv1.y);
            ffma2(acc1, wreg[16 + 4 * u + 3], hv1.y);
            if (u < 2) {
                ffma2(acc2, wreg[32 + 4 * u],     hv0.x);
                ffma2(acc2, wreg[32 + 4 * u + 1], hv0.y);
                ffma2(acc2, wreg[32 + 4 * u + 2], hv1.x);
                ffma2(acc2, wreg[32 + 4 * u + 3], hv1.y);
            } else {
                uint4 wv2 = wsp[(4 + (u - 2)) * 512];
                ffma2(acc2, bf2pair(wv2.x), hv0.x);
                ffma2(acc2, bf2pair(wv2.y), hv0.y);
                ffma2(acc2, bf2pair(wv2.z), hv1.x);
                ffma2(acc2, bf2pair(wv2.w), hv1.y);
            }
            ffma2(acc3, bf2pair(wv.x), hv0.x);
            ffma2(acc3, bf2pair(wv.y), hv0.y);
            ffma2(acc3, bf2pair(wv.z), hv1.x);
            ffma2(acc3, bf2pair(wv.w), hv1.y);
        }

        float p0, p1, p2, p3, lo, hi;
        unpack2(acc0, lo, hi); p0 = lo + hi;
        unpack2(acc1, lo, hi); p1 = lo + hi;
        unpack2(acc2, lo, hi); p2 = lo + hi;
        unpack2(acc3, lo, hi); p3 = lo + hi;

        float s0 = p0 + __shfl_xor_sync(0xffffffffu, p1, 1);
        float s1 = p2 + __shfl_xor_sync(0xffffffffu, p3, 1);
        float z  = s0 + __shfl_xor_sync(0xffffffffu, s1, 2);

        float a = fmaf(sc, tanhaf(sc * z), scb);

        float a1 = __shfl_xor_sync(0xffffffffu, a, 1);
        float a2 = __shfl_xor_sync(0xffffffffu, a, 2);
        float a3 = __shfl_xor_sync(0xffffffffu, a1, 2);
        float gi_ = pick4(a, a1, a2, a3, q);
        float gf_ = pick4(a, a1, a2, a3, q ^ 1);
        float gg_ = pick4(a, a1, a2, a3, q ^ 2);
        float go_ = pick4(a, a1, a2, a3, q ^ 3);

        c = fmaf(gf_, c, gi_ * gg_);
        float h = go_ * tanhaf(c);
        if (hwriter) S->hsk[(t + 1) & 1][hwidx] = h;

        xgq = xg_nxt;
        __syncthreads();
    }

    if (tid < 256) {
        int cls = tid >> 7;
        int jj  = tid & 127;
        float hv = S->hsk[0][(jj >> 5) * 36 + (jj & 31)];
        S->hred[tid] = hv * W_fc[cls * HID + jj];
    }
    __syncthreads();
    if (tid < 2) {
        float s = b_fc[tid];
#pragma unroll 8
        for (int jj = 0; jj < HID; jj++) s += S->hred[tid * HID + jj];
        out[b * 2 + tid] = s;
    }
}

// =====================================================================
extern "C" void kernel_launch(void* const* d_in, const int* in_sizes, int n_in,
                              void* d_out, int out_size)
{
    const void*  x     = d_in[0];
    const float* emb   = (const float*)d_in[1];
    const float* W_ih  = (const float*)d_in[2];
    const float* W_hh  = (const float*)d_in[3];
    const float* b_ih  = (const float*)d_in[4];
    const float* b_hh  = (const float*)d_in[5];
    const float* W_fc  = (const float*)d_in[6];
    const float* b_fc  = (const float*)d_in[7];
    float* out = (float*)d_out;

    __nv_bfloat16 *p_embh, *p_embl, *p_wih_h, *p_wih_l;
    cudaGetSymbolAddress((void**)&p_embh,  g_embh);
    cudaGetSymbolAddress((void**)&p_embl,  g_embl);
    cudaGetSymbolAddress((void**)&p_wih_h, g_wih_h);
    cudaGetSymbolAddress((void**)&p_wih_l, g_wih_l);

    conv_split_fused<<<CONV_BLOCKS, 256>>>(emb, W_ih, p_embh, p_embl, p_wih_h, p_wih_l);

    cudaFuncSetAttribute(table_wmma_kernel, cudaFuncAttributeMaxDynamicSharedMemorySize, TB_SMEM);
    dim3 tgrid(G4 / 128, (VOCAB + 127) / 128);   // 4 x 393 (gate-major: siblings adjacent)
    table_wmma_kernel<<<tgrid, 256, TB_SMEM>>>(b_ih, b_hh);

    const int smem_bytes = (int)sizeof(LstmSmem);
    cudaFuncSetAttribute(lstm_kernel, cudaFuncAttributeMaxDynamicSharedMemorySize, smem_bytes);
    lstm_kernel<<<BATCH, 512, smem_bytes>>>(x, W_hh, W_fc, b_fc, out);
}